// round 15
// baseline (speedup 1.0000x reference)
#include <cuda_runtime.h>

// Fixed shapes from reference setup_inputs
#define BN  16
#define HH  448
#define WW  1024
#define HWN (HH * WW)

#define TX 32
#define TY 8
#define NBUCK 64
#define TOTAL_BLOCKS ((WW / TX) * (HH / TY) * BN)   // 32*56*16 = 28672

// Bucketed double partials + completion ticket. Zero at module load; the last
// block re-zeroes them after writing the output, so every kernel_launch
// (correctness run and each graph replay) starts from zeros.
__device__ double       g_part[2][NBUCK];
__device__ unsigned int g_count;

__global__ __launch_bounds__(256, 8) void elbo_fused_kernel(
    const float* __restrict__ mean,
    const float* __restrict__ log_var,
    const float* __restrict__ img1,
    const float* __restrict__ img2,
    const float* __restrict__ target,
    const float* __restrict__ eps,
    float* __restrict__ out)
{
    __shared__ float su[TY + 1][TX + 1];
    __shared__ float sv[TY + 1][TX + 1];
    __shared__ float red_e[8];
    __shared__ float red_p[8];
    __shared__ unsigned int s_last;
    __shared__ double fin_e[NBUCK];
    __shared__ double fin_p[NBUCK];

    const int b   = blockIdx.z;
    const int bx0 = blockIdx.x * TX;
    const int by0 = blockIdx.y * TY;
    const int tid = threadIdx.x;
    const int tx  = tid & 31;
    const int ty  = tid >> 5;

    const size_t base2 = (size_t)b * 2 * HWN;
    const size_t base3 = (size_t)b * 3 * HWN;
    const float* __restrict__ mu = mean    + base2;
    const float* __restrict__ lv = log_var + base2;
    const float* __restrict__ ep = eps     + base2;
    const float* __restrict__ tg = target  + base2;
    const float* __restrict__ i1 = img1    + base3;
    const float* __restrict__ i2 = img2    + base3;

    // ---- Flow tile with +1 halo (right & bottom), border-clamped.
    // Clamp => dx/dy = 0 at the border, matching the reference's zero-padding.
    for (int i = tid; i < (TX + 1) * (TY + 1); i += 256) {
        const int lx = i % (TX + 1);
        const int ly = i / (TX + 1);
        const int gx = min(bx0 + lx, WW - 1);
        const int gy = min(by0 + ly, HH - 1);
        const int id = gy * WW + gx;
        su[ly][lx] = mu[id]       + __expf(0.5f * lv[id])       * ep[id];
        sv[ly][lx] = mu[HWN + id] + __expf(0.5f * lv[HWN + id]) * ep[HWN + id];
    }
    __syncthreads();

    const int x   = bx0 + tx;    // grid exactly tiles 1024x448
    const int y   = by0 + ty;
    const int idx = y * WW + x;

    const float u = su[ty][tx];
    const float v = sv[ty][tx];

    // ---- Data term: bilinear warp of img2 at (x+u, y+v), clamped taps,
    // unclamped weights (matches reference).
    const float fx  = (float)x + u;
    const float fy  = (float)y + v;
    const float x0f = floorf(fx);
    const float y0f = floorf(fy);
    const float wx  = fx - x0f;
    const float wy  = fy - y0f;
    const int x0 = min(max((int)x0f, 0), WW - 1);
    const int x1 = min(x0 + 1, WW - 1);
    const int y0 = min(max((int)y0f, 0), HH - 1);
    const int y1 = min(y0 + 1, HH - 1);
    const int i00 = y0 * WW + x0;
    const int i01 = y0 * WW + x1;
    const int i10 = y1 * WW + x0;
    const int i11 = y1 * WW + x1;

    const float w00 = (1.f - wy) * (1.f - wx);
    const float w01 = (1.f - wy) * wx;
    const float w10 = wy * (1.f - wx);
    const float w11 = wy * wx;

    float A = 0.f;
    #pragma unroll
    for (int c = 0; c < 3; ++c) {
        const float* __restrict__ p = i2 + c * HWN;
        const float warped = w00 * __ldg(p + i00) + w01 * __ldg(p + i01)
                           + w10 * __ldg(p + i10) + w11 * __ldg(p + i11);
        const float d = i1[c * HWN + idx] - warped;
        A = fmaf(d, d, A);
    }
    const float pen_data = sqrtf(A + 1e-5f);

    // ---- Smoothness term from shared tile
    const float dxu = su[ty][tx + 1] - u;
    const float dxv = sv[ty][tx + 1] - v;
    const float dyu = su[ty + 1][tx] - u;
    const float dyv = sv[ty + 1][tx] - v;
    const float pen_sm = sqrtf(dxu * dxu + dxv * dxv + dyu * dyu + dyv * dyv + 1e-5f);

    // ---- log_var and EPE contributions (own pixel; L1 hits from halo pass)
    const float lv0 = lv[idx];
    const float lv1 = lv[HWN + idx];
    const float d0  = mu[idx]       - tg[idx];
    const float d1  = mu[HWN + idx] - tg[HWN + idx];
    const float epe = sqrtf(d0 * d0 + d1 * d1);

    float acc_e = pen_data + pen_sm - 0.5f * (lv0 + lv1);
    float acc_p = epe;

    // ---- Block reduction -> bucketed double RED + release-ordered ticket
    #pragma unroll
    for (int off = 16; off; off >>= 1) {
        acc_e += __shfl_down_sync(0xFFFFFFFFu, acc_e, off);
        acc_p += __shfl_down_sync(0xFFFFFFFFu, acc_p, off);
    }
    if (tx == 0) { red_e[ty] = acc_e; red_p[ty] = acc_p; }
    __syncthreads();
    if (tid == 0) {
        float se = 0.f, sp = 0.f;
        #pragma unroll
        for (int i = 0; i < 8; ++i) { se += red_e[i]; sp += red_p[i]; }
        const int bk = (blockIdx.x + 32 * blockIdx.y + 7 * blockIdx.z) & (NBUCK - 1);
        atomicAdd(&g_part[0][bk], (double)se);   // fire-and-forget RED.ADD.F64 (L2)
        atomicAdd(&g_part[1][bk], (double)sp);
        // Release-ordered ticket: orders the REDs before the count increment
        // WITHOUT a gpu-scope membar (no CCTL.IVALL L1 flush per block).
        unsigned int old;
        asm volatile("atom.release.gpu.add.u32 %0, [%1], %2;"
                     : "=r"(old) : "l"(&g_count), "r"(1u) : "memory");
        s_last = (old == TOTAL_BLOCKS - 1) ? 1u : 0u;
    }
    __syncthreads();

    // ---- Last block: fold buckets, emit outputs, reset state for next replay
    if (s_last) {
        if (tid == 0) {
            asm volatile("fence.acquire.gpu;" ::: "memory");  // once, whole grid
        }
        __syncthreads();
        if (tid < NBUCK) {
            fin_e[tid] = __ldcg(&g_part[0][tid]);   // L2-coherent reads
            fin_p[tid] = __ldcg(&g_part[1][tid]);
        }
        __syncthreads();
        if (tid == 0) {
            double a = 0.0, p = 0.0;
            #pragma unroll
            for (int i = 0; i < NBUCK; ++i) { a += fin_e[i]; p += fin_p[i]; }
            out[0] = (float)(a / (double)BN);
            out[1] = (float)(p / ((double)BN * (double)HWN));
            g_count = 0u;
        }
        if (tid < NBUCK) {
            g_part[0][tid] = 0.0;
            g_part[1][tid] = 0.0;
        }
    }
}

extern "C" void kernel_launch(void* const* d_in, const int* in_sizes, int n_in,
                              void* d_out, int out_size) {
    const float* mean    = (const float*)d_in[0];
    const float* log_var = (const float*)d_in[1];
    const float* img1    = (const float*)d_in[2];
    const float* img2    = (const float*)d_in[3];
    const float* target  = (const float*)d_in[4];
    const float* eps     = (const float*)d_in[5];
    float* out = (float*)d_out;

    dim3 grid(WW / TX, HH / TY, BN);   // 32 x 56 x 16 = 28672 blocks
    elbo_fused_kernel<<<grid, 256>>>(mean, log_var, img1, img2, target, eps, out);
}

// round 16
// speedup vs baseline: 1.0549x; 1.0549x over previous
#include <cuda_runtime.h>

// Fixed shapes from reference setup_inputs
#define BN  16
#define HH  448
#define WW  1024
#define HWN (HH * WW)

#define TX 32
#define TY 8
#define NBUCK 64

// Bucketed double partials. Zero at module load; elbo_finalize_kernel
// re-zeroes them after reading, so every kernel_launch invocation
// (correctness run and each graph replay) starts from zeros.
__device__ double g_part[2][NBUCK];

__global__ __launch_bounds__(256, 8) void elbo_main_kernel(
    const float* __restrict__ mean,
    const float* __restrict__ log_var,
    const float* __restrict__ img1,
    const float* __restrict__ img2,
    const float* __restrict__ target,
    const float* __restrict__ eps)
{
    __shared__ float su[TY + 1][TX + 1];
    __shared__ float sv[TY + 1][TX + 1];
    __shared__ float red_e[8];
    __shared__ float red_p[8];

    const int b   = blockIdx.z;
    const int bx0 = blockIdx.x * TX;
    const int by0 = blockIdx.y * TY;
    const int tid = threadIdx.x;
    const int tx  = tid & 31;
    const int ty  = tid >> 5;

    const size_t base2 = (size_t)b * 2 * HWN;
    const size_t base3 = (size_t)b * 3 * HWN;
    const float* __restrict__ mu = mean    + base2;
    const float* __restrict__ lv = log_var + base2;
    const float* __restrict__ ep = eps     + base2;
    const float* __restrict__ tg = target  + base2;
    const float* __restrict__ i1 = img1    + base3;
    const float* __restrict__ i2 = img2    + base3;

    float acc_e = 0.f;
    float acc_p = 0.f;

    // ---- Flow tile with +1 halo (right & bottom), border-clamped.
    // Clamp => dx/dy = 0 at the border, matching the reference's zero-padding.
    // For interior (non-halo) entries, also accumulate the log_var and EPE
    // contributions HERE, reusing mu/lv already in registers (each image pixel
    // is interior to exactly one block, so each contributes exactly once).
    for (int i = tid; i < (TX + 1) * (TY + 1); i += 256) {
        const int lx = i % (TX + 1);
        const int ly = i / (TX + 1);
        const int gx = min(bx0 + lx, WW - 1);
        const int gy = min(by0 + ly, HH - 1);
        const int id = gy * WW + gx;
        const float m0 = mu[id];
        const float m1 = mu[HWN + id];
        const float l0 = lv[id];
        const float l1 = lv[HWN + id];
        su[ly][lx] = m0 + __expf(0.5f * l0) * ep[id];
        sv[ly][lx] = m1 + __expf(0.5f * l1) * ep[HWN + id];
        if (lx < TX && ly < TY) {
            const float d0 = m0 - tg[id];
            const float d1 = m1 - tg[HWN + id];
            acc_p += sqrtf(d0 * d0 + d1 * d1);
            acc_e -= 0.5f * (l0 + l1);
        }
    }
    __syncthreads();

    const int x   = bx0 + tx;    // grid exactly tiles 1024x448
    const int y   = by0 + ty;
    const int idx = y * WW + x;

    const float u = su[ty][tx];
    const float v = sv[ty][tx];

    // ---- Data term: bilinear warp of img2 at (x+u, y+v), clamped taps,
    // unclamped weights (matches reference).
    const float fx  = (float)x + u;
    const float fy  = (float)y + v;
    const float x0f = floorf(fx);
    const float y0f = floorf(fy);
    const float wx  = fx - x0f;
    const float wy  = fy - y0f;
    const int x0 = min(max((int)x0f, 0), WW - 1);
    const int x1 = min(x0 + 1, WW - 1);
    const int y0 = min(max((int)y0f, 0), HH - 1);
    const int y1 = min(y0 + 1, HH - 1);
    const int i00 = y0 * WW + x0;
    const int i01 = y0 * WW + x1;
    const int i10 = y1 * WW + x0;
    const int i11 = y1 * WW + x1;

    const float w00 = (1.f - wy) * (1.f - wx);
    const float w01 = (1.f - wy) * wx;
    const float w10 = wy * (1.f - wx);
    const float w11 = wy * wx;

    float A = 0.f;
    #pragma unroll
    for (int c = 0; c < 3; ++c) {
        const float* __restrict__ p = i2 + c * HWN;
        const float warped = w00 * __ldg(p + i00) + w01 * __ldg(p + i01)
                           + w10 * __ldg(p + i10) + w11 * __ldg(p + i11);
        const float d = i1[c * HWN + idx] - warped;
        A = fmaf(d, d, A);
    }
    const float pen_data = sqrtf(A + 1e-5f);

    // ---- Smoothness term from shared tile
    const float dxu = su[ty][tx + 1] - u;
    const float dxv = sv[ty][tx + 1] - v;
    const float dyu = su[ty + 1][tx] - u;
    const float dyv = sv[ty + 1][tx] - v;
    const float pen_sm = sqrtf(dxu * dxu + dxv * dxv + dyu * dyu + dyv * dyv + 1e-5f);

    acc_e += pen_data + pen_sm;

    // ---- Block reduction -> bucketed double RED (fire-and-forget, NO fence)
    #pragma unroll
    for (int off = 16; off; off >>= 1) {
        acc_e += __shfl_down_sync(0xFFFFFFFFu, acc_e, off);
        acc_p += __shfl_down_sync(0xFFFFFFFFu, acc_p, off);
    }
    if (tx == 0) { red_e[ty] = acc_e; red_p[ty] = acc_p; }
    __syncthreads();
    if (tid == 0) {
        float se = 0.f, sp = 0.f;
        #pragma unroll
        for (int i = 0; i < 8; ++i) { se += red_e[i]; sp += red_p[i]; }
        const int bk = (blockIdx.x + 32 * blockIdx.y + 7 * blockIdx.z) & (NBUCK - 1);
        atomicAdd(&g_part[0][bk], (double)se);   // RED.ADD.F64 to L2
        atomicAdd(&g_part[1][bk], (double)sp);
    }
}

__global__ void elbo_finalize_kernel(float* __restrict__ out) {
    __shared__ double se[NBUCK];
    __shared__ double sp[NBUCK];
    const int t = threadIdx.x;
    se[t] = g_part[0][t];
    sp[t] = g_part[1][t];
    g_part[0][t] = 0.0;          // reset for the next replay (deterministic)
    g_part[1][t] = 0.0;
    __syncthreads();
    if (t == 0) {
        double a = 0.0, p = 0.0;
        #pragma unroll
        for (int i = 0; i < NBUCK; ++i) { a += se[i]; p += sp[i]; }
        out[0] = (float)(a / (double)BN);
        out[1] = (float)(p / ((double)BN * (double)HWN));
    }
}

extern "C" void kernel_launch(void* const* d_in, const int* in_sizes, int n_in,
                              void* d_out, int out_size) {
    const float* mean    = (const float*)d_in[0];
    const float* log_var = (const float*)d_in[1];
    const float* img1    = (const float*)d_in[2];
    const float* img2    = (const float*)d_in[3];
    const float* target  = (const float*)d_in[4];
    const float* eps     = (const float*)d_in[5];
    float* out = (float*)d_out;

    dim3 grid(WW / TX, HH / TY, BN);   // 32 x 56 x 16 = 28672 blocks
    elbo_main_kernel<<<grid, 256>>>(mean, log_var, img1, img2, target, eps);
    elbo_finalize_kernel<<<1, NBUCK>>>(out);
}